// round 4
// baseline (speedup 1.0000x reference)
#include <cuda_runtime.h>
#include <cstddef>

// AggFeatureModel: per-row numeric aggregates + per-category (count, mean, std)
// histograms for mcc (100 cats) and tr_type (50 cats), plus distinct counts.
//
// Strategy: 1 warp per row. Each lane owns a PRIVATE SMEM column of every
// histogram bin (stride-32 layout -> bank == lane -> conflict-free RMW, no
// races, NO atomics). sum+sumsq fused as float2 (one LDS.64/STS.64 RMW).
// Cross-lane fold uses rotated addressing (lane+i)&31, conflict-free.
// 4 warps (4 rows) per CTA; 230,400 B dynamic SMEM (1 CTA/SM).
// Depth-3 register pipeline on the global stream (~9 LDG.128/warp in flight);
// first-stage loads issue BEFORE SMEM zeroing to overlap DRAM latency.

#define EPSF 1e-9f

constexpr int NC_M = 100;                         // mcc categories
constexpr int NC_T = 50;                          // tr_type categories
constexpr int OUTC = 456;                         // output columns per row
constexpr int WARP_FLOATS = (3 * NC_M + 3 * NC_T) * 32;   // 14400 floats = 57.6 KB
constexpr int SMEM_BYTES  = 4 * WARP_FLOATS * 4;          // 230400 B (<= 232448 cap)

__global__ __launch_bounds__(128, 1)
void agg_kernel(const float* __restrict__ amount,
                const int*   __restrict__ mcc,
                const int*   __restrict__ trt,
                const int*   __restrict__ seq,
                float*       __restrict__ out,
                int B, int T)
{
    extern __shared__ float sh[];
    const int lane = threadIdx.x & 31;
    const int w    = threadIdx.x >> 5;
    const int row  = blockIdx.x * 4 + w;
    const bool live = (row < B);

    float*  hb   = sh + w * WARP_FLOATS;
    float2* SQM  = reinterpret_cast<float2*>(hb);                 // [NC_M][32] (sum,ss)
    float*  CNTM = hb + 2 * NC_M * 32;                            // [NC_M][32]
    float2* SQT  = reinterpret_cast<float2*>(hb + 3 * NC_M * 32); // [NC_T][32]
    float*  CNTT = hb + 3 * NC_M * 32 + 2 * NC_T * 32;            // [NC_T][32]

    const float* arow = amount + (size_t)row * T;
    const int*   mrow = mcc    + (size_t)row * T;
    const int*   trow = trt    + (size_t)row * T;

    const int nIter = T >> 7;               // 4 elements/lane/iter, 128/warp/iter

    // ---- issue first pipeline stages BEFORE zeroing: DRAM latency overlaps
    // the ~450-cycle SMEM zero phase.
    float4 A[3]; int4 M[3], Tt[3];
    if (live) {
        #pragma unroll
        for (int p = 0; p < 3; p++) {
            if (p < nIter) {
                const int b = (p << 7) + (lane << 2);
                A[p]  = *reinterpret_cast<const float4*>(arow + b);
                M[p]  = *reinterpret_cast<const int4*>(mrow + b);
                Tt[p] = *reinterpret_cast<const int4*>(trow + b);
            }
        }
    }

    // ---- zero this warp's private histogram region (float4 stores) ----
    float4* hb4 = reinterpret_cast<float4*>(hb);
    for (int i = lane; i < WARP_FLOATS / 4; i += 32)
        hb4[i] = make_float4(0.f, 0.f, 0.f, 0.f);
    __syncwarp();

    if (live) {
        float rs = 0.f, rss = 0.f;          // row-level sum / sumsq

        #pragma unroll 3
        for (int j = 0; j < nIter; j++) {
            const int cur = j % 3;
            const float4 a = A[cur];
            const int4   m = M[cur];
            const int4   t = Tt[cur];

            if (j + 3 < nIter) {            // refill this slot 3 stages ahead
                const int nb = ((j + 3) << 7) + (lane << 2);
                A[cur]  = *reinterpret_cast<const float4*>(arow + nb);
                M[cur]  = *reinterpret_cast<const int4*>(mrow + nb);
                Tt[cur] = *reinterpret_cast<const int4*>(trow + nb);
            }

            const float vs[4] = {a.x, a.y, a.z, a.w};
            const int   ms[4] = {m.x, m.y, m.z, m.w};
            const int   ts[4] = {t.x, t.y, t.z, t.w};

            #pragma unroll
            for (int k = 0; k < 4; k++) {
                const float v  = vs[k];
                const float vv = __fmul_rn(v, v);   // rounded product (match ref)
                rs  += v;
                rss += vv;

                const unsigned cm = (unsigned)ms[k];
                if (cm < (unsigned)NC_M) {
                    const int o = (int)(cm << 5) + lane;   // private copy: bank==lane
                    float2 p = SQM[o];
                    p.x += v; p.y += vv;
                    SQM[o]  = p;
                    CNTM[o] += 1.f;
                }
                const unsigned ct = (unsigned)ts[k];
                if (ct < (unsigned)NC_T) {
                    const int o = (int)(ct << 5) + lane;
                    float2 p = SQT[o];
                    p.x += v; p.y += vv;
                    SQT[o]  = p;
                    CNTT[o] += 1.f;
                }
            }
        }
        __syncwarp();

        float* orow = out + (size_t)row * OUTC;

        // ---- per-category fold + epilogue. Rotated lane access: conflict-free.
        int dm = 0;
        for (int c = lane; c < NC_M; c += 32) {
            float s = 0.f, q = 0.f, n = 0.f;
            const int cb = c << 5;
            #pragma unroll 8
            for (int i = 0; i < 32; i++) {
                const int l2 = (lane + i) & 31;
                const float2 p = SQM[cb + l2];
                s += p.x; q += p.y;
                n += CNTM[cb + l2];
            }
            const float ecnt = (c > 0) ? n : 0.f;
            const float den  = ecnt + EPSF;
            const float mean = __fdiv_rn(s, den);
            // NO fma contraction: for cnt==1 this must cancel to exactly 0.
            const float aa = fmaxf(__fsub_rn(q, __fdiv_rn(__fmul_rn(s, s), den)), 0.f);
            const float sd = sqrtf(__fdiv_rn(aa, fmaxf(ecnt - 1.f, 0.f) + EPSF));
            orow[4   + c] = ecnt;
            orow[104 + c] = mean;
            orow[204 + c] = sd;
            dm += (ecnt > 0.f) ? 1 : 0;
        }

        int dt = 0;
        for (int c = lane; c < NC_T; c += 32) {
            float s = 0.f, q = 0.f, n = 0.f;
            const int cb = c << 5;
            #pragma unroll 8
            for (int i = 0; i < 32; i++) {
                const int l2 = (lane + i) & 31;
                const float2 p = SQT[cb + l2];
                s += p.x; q += p.y;
                n += CNTT[cb + l2];
            }
            const float ecnt = (c > 0) ? n : 0.f;
            const float den  = ecnt + EPSF;
            const float mean = __fdiv_rn(s, den);
            const float aa = fmaxf(__fsub_rn(q, __fdiv_rn(__fmul_rn(s, s), den)), 0.f);
            const float sd = sqrtf(__fdiv_rn(aa, fmaxf(ecnt - 1.f, 0.f) + EPSF));
            orow[304 + c] = ecnt;
            orow[354 + c] = mean;
            orow[404 + c] = sd;
            dt += (ecnt > 0.f) ? 1 : 0;
        }

        dm = __reduce_add_sync(0xffffffffu, dm);
        dt = __reduce_add_sync(0xffffffffu, dt);

        // ---- row-level reduction (butterfly) ----
        #pragma unroll
        for (int off = 16; off; off >>= 1) {
            rs  += __shfl_xor_sync(0xffffffffu, rs,  off);
            rss += __shfl_xor_sync(0xffffffffu, rss, off);
        }

        if (lane == 0) {
            const float sl  = (float)seq[row];
            const float den = sl + EPSF;
            orow[0] = sl;
            orow[1] = rs;
            orow[2] = __fdiv_rn(rs, den);
            const float aa = fmaxf(__fsub_rn(rss, __fdiv_rn(__fmul_rn(rs, rs), den)), 0.f);
            orow[3] = sqrtf(__fdiv_rn(aa, fmaxf(sl - 1.f, 0.f) + EPSF));
            orow[454] = (float)dm;
            orow[455] = (float)dt;
        }
    }
}

extern "C" void kernel_launch(void* const* d_in, const int* in_sizes, int n_in,
                              void* d_out, int out_size)
{
    const float* amount = (const float*)d_in[0];
    const int*   mcc    = (const int*)d_in[1];
    const int*   trt    = (const int*)d_in[2];
    const int*   seq    = (const int*)d_in[3];
    float*       out    = (float*)d_out;

    const int B = in_sizes[3];            // seq_lens element count
    const int T = in_sizes[0] / B;        // 2048

    // Opt in to 230.4 KB dynamic SMEM (host attribute; no allocation; safe
    // under graph capture).
    cudaFuncSetAttribute(agg_kernel, cudaFuncAttributeMaxDynamicSharedMemorySize,
                         SMEM_BYTES);

    const int grid = (B + 3) / 4;         // 4 rows (warps) per CTA
    agg_kernel<<<grid, 128, SMEM_BYTES>>>(amount, mcc, trt, seq, out, B, T);
}

// round 10
// speedup vs baseline: 1.5417x; 1.5417x over previous
#include <cuda_runtime.h>
#include <cstddef>

// AggFeatureModel: per-row numeric aggregates + per-category (count, mean, std)
// histograms for mcc (100 cats) and tr_type (50 cats), plus distinct counts.
//
// Design (from R4 ncu: latency-bound, occ 6.2%, issue 17%, no busy pipe):
//  * table entry fused to float4 (sum, sumsq, cnt, pad) -> 2 RMW chains/elem
//  * 8 copies/warp: quad {l, l^8, l^16, l^24} shares a copy. Exact dedup via
//    3 shfl_xor exchanges of a PACKED (mcc<<16|trt) word + 3 value exchanges
//    (6 SHFL/element); lowest equal-cat lane does one combined RMW.
//    NO atomics, no races (truth table verified over all equality patterns).
//  * 19.2 KB/warp -> 12 warps/CTA (230,400 B smem) -> 3 warps/SMSP to
//    interleave the LDS->STS ordering chains.
//  * depth-3 LDG.128 pipeline issued before SMEM zeroing.
// FROZEN from R5 pending first successful bench (attribution discipline).

#define EPSF 1e-9f

constexpr int NC_M = 100;
constexpr int NC_T = 50;
constexpr int OUTC = 456;
constexpr int COPIES = 8;
constexpr int WARPS  = 12;
constexpr int WARP_F4 = (NC_M + NC_T) * COPIES;        // 1200 float4 = 19200 B
constexpr int SMEM_BYTES = WARPS * WARP_F4 * 16;       // 230400 B (<= 232448)

__global__ __launch_bounds__(WARPS * 32, 1)
void agg_kernel(const float* __restrict__ amount,
                const int*   __restrict__ mcc,
                const int*   __restrict__ trt,
                const int*   __restrict__ seq,
                float*       __restrict__ out,
                int B, int T)
{
    extern __shared__ float4 sh4[];
    const int lane = threadIdx.x & 31;
    const int w    = threadIdx.x >> 5;
    const int row  = blockIdx.x * WARPS + w;
    const bool live = (row < B);

    float4* TBL_M = sh4 + w * WARP_F4;            // [NC_M][8] (sum,ss,cnt,pad)
    float4* TBL_T = TBL_M + NC_M * COPIES;        // [NC_T][8]
    const int copy = lane & 7;
    const bool low8  = (lane & 8)  != 0;          // partner l^8  is lower
    const bool low16 = (lane & 16) != 0;          // partners l^16, l^24 are lower

    const float* arow = amount + (size_t)row * T;
    const int*   mrow = mcc    + (size_t)row * T;
    const int*   trow = trt    + (size_t)row * T;
    const int nIter = T >> 7;                     // 4 elements/lane per iter

    // issue first pipeline stages BEFORE zeroing (overlap DRAM latency)
    float4 A[3]; int4 M[3], Tt[3];
    if (live) {
        #pragma unroll
        for (int p = 0; p < 3; p++) {
            if (p < nIter) {
                const int b = (p << 7) + (lane << 2);
                A[p]  = *reinterpret_cast<const float4*>(arow + b);
                M[p]  = *reinterpret_cast<const int4*>(mrow + b);
                Tt[p] = *reinterpret_cast<const int4*>(trow + b);
            }
        }
    }

    // zero this warp's table
    for (int i = lane; i < WARP_F4; i += 32)
        TBL_M[i] = make_float4(0.f, 0.f, 0.f, 0.f);
    __syncwarp();

    if (live) {
        float rs = 0.f, rss = 0.f;

        #pragma unroll 3
        for (int j = 0; j < nIter; j++) {
            const int cur = j % 3;
            const float4 a = A[cur];
            const int4   m = M[cur];
            const int4   t = Tt[cur];
            if (j + 3 < nIter) {
                const int nb = ((j + 3) << 7) + (lane << 2);
                A[cur]  = *reinterpret_cast<const float4*>(arow + nb);
                M[cur]  = *reinterpret_cast<const int4*>(mrow + nb);
                Tt[cur] = *reinterpret_cast<const int4*>(trow + nb);
            }

            const float vs[4] = {a.x, a.y, a.z, a.w};
            const int   ms[4] = {m.x, m.y, m.z, m.w};
            const int   ts[4] = {t.x, t.y, t.z, t.w};

            #pragma unroll
            for (int k = 0; k < 4; k++) {
                const float v  = vs[k];
                const float vv = __fmul_rn(v, v);
                rs += v; rss += vv;

                // one packed word carries BOTH categories
                const unsigned pk = ((unsigned)ms[k] << 16) | (unsigned)ts[k];
                const unsigned p8  = __shfl_xor_sync(0xffffffffu, pk, 8);
                const unsigned p16 = __shfl_xor_sync(0xffffffffu, pk, 16);
                const unsigned p24 = __shfl_xor_sync(0xffffffffu, pk, 24);
                const float v8  = __shfl_xor_sync(0xffffffffu, v, 8);
                const float v16 = __shfl_xor_sync(0xffffffffu, v, 16);
                const float v24 = __shfl_xor_sync(0xffffffffu, v, 24);
                const float w8  = __fmul_rn(v8,  v8);
                const float w16 = __fmul_rn(v16, v16);
                const float w24 = __fmul_rn(v24, v24);
                const unsigned x8 = pk ^ p8, x16 = pk ^ p16, x24 = pk ^ p24;

                // ---- mcc table (high halfword) ----
                {
                    const bool e8  = (x8  & 0xFFFF0000u) == 0u;
                    const bool e16 = (x16 & 0xFFFF0000u) == 0u;
                    const bool e24 = (x24 & 0xFFFF0000u) == 0u;
                    const bool lead = !((e8 & low8) | (e16 & low16) | (e24 & low16));
                    if (lead) {
                        float sv = v, sw = vv, sc = 1.f;
                        if (e8)  { sv += v8;  sw += w8;  sc += 1.f; }
                        if (e16) { sv += v16; sw += w16; sc += 1.f; }
                        if (e24) { sv += v24; sw += w24; sc += 1.f; }
                        const unsigned c = pk >> 16;
                        if (c < (unsigned)NC_M) {
                            const int o = (int)c * COPIES + copy;   // conflict-free
                            float4 p = TBL_M[o];
                            p.x += sv; p.y += sw; p.z += sc;
                            TBL_M[o] = p;
                        }
                    }
                }
                // ---- tr_type table (low halfword) ----
                {
                    const bool e8  = (x8  & 0x0000FFFFu) == 0u;
                    const bool e16 = (x16 & 0x0000FFFFu) == 0u;
                    const bool e24 = (x24 & 0x0000FFFFu) == 0u;
                    const bool lead = !((e8 & low8) | (e16 & low16) | (e24 & low16));
                    if (lead) {
                        float sv = v, sw = vv, sc = 1.f;
                        if (e8)  { sv += v8;  sw += w8;  sc += 1.f; }
                        if (e16) { sv += v16; sw += w16; sc += 1.f; }
                        if (e24) { sv += v24; sw += w24; sc += 1.f; }
                        const unsigned c = pk & 0xFFFFu;
                        if (c < (unsigned)NC_T) {
                            const int o = (int)c * COPIES + copy;
                            float4 p = TBL_T[o];
                            p.x += sv; p.y += sw; p.z += sc;
                            TBL_T[o] = p;
                        }
                    }
                }
            }
        }
        __syncwarp();

        float* orow = out + (size_t)row * OUTC;

        // ---- fold 8 copies per category + epilogue (rotated: conflict-free)
        int dm = 0;
        for (int c = lane; c < NC_M; c += 32) {
            float s = 0.f, q = 0.f, n = 0.f;
            #pragma unroll
            for (int i = 0; i < COPIES; i++) {
                const float4 p = TBL_M[c * COPIES + ((i + lane) & 7)];
                s += p.x; q += p.y; n += p.z;
            }
            const float ecnt = (c > 0) ? n : 0.f;
            const float den  = ecnt + EPSF;
            const float mean = __fdiv_rn(s, den);
            // no FMA contraction: cnt==1 must cancel to exactly 0
            const float aa = fmaxf(__fsub_rn(q, __fdiv_rn(__fmul_rn(s, s), den)), 0.f);
            const float sd = sqrtf(__fdiv_rn(aa, fmaxf(ecnt - 1.f, 0.f) + EPSF));
            orow[4   + c] = ecnt;
            orow[104 + c] = mean;
            orow[204 + c] = sd;
            dm += (ecnt > 0.f) ? 1 : 0;
        }
        int dt = 0;
        for (int c = lane; c < NC_T; c += 32) {
            float s = 0.f, q = 0.f, n = 0.f;
            #pragma unroll
            for (int i = 0; i < COPIES; i++) {
                const float4 p = TBL_T[c * COPIES + ((i + lane) & 7)];
                s += p.x; q += p.y; n += p.z;
            }
            const float ecnt = (c > 0) ? n : 0.f;
            const float den  = ecnt + EPSF;
            const float mean = __fdiv_rn(s, den);
            const float aa = fmaxf(__fsub_rn(q, __fdiv_rn(__fmul_rn(s, s), den)), 0.f);
            const float sd = sqrtf(__fdiv_rn(aa, fmaxf(ecnt - 1.f, 0.f) + EPSF));
            orow[304 + c] = ecnt;
            orow[354 + c] = mean;
            orow[404 + c] = sd;
            dt += (ecnt > 0.f) ? 1 : 0;
        }

        dm = __reduce_add_sync(0xffffffffu, dm);
        dt = __reduce_add_sync(0xffffffffu, dt);

        #pragma unroll
        for (int off = 16; off; off >>= 1) {
            rs  += __shfl_xor_sync(0xffffffffu, rs,  off);
            rss += __shfl_xor_sync(0xffffffffu, rss, off);
        }

        if (lane == 0) {
            const float sl  = (float)seq[row];
            const float den = sl + EPSF;
            orow[0] = sl;
            orow[1] = rs;
            orow[2] = __fdiv_rn(rs, den);
            const float aa = fmaxf(__fsub_rn(rss, __fdiv_rn(__fmul_rn(rs, rs), den)), 0.f);
            orow[3] = sqrtf(__fdiv_rn(aa, fmaxf(sl - 1.f, 0.f) + EPSF));
            orow[454] = (float)dm;
            orow[455] = (float)dt;
        }
    }
}

extern "C" void kernel_launch(void* const* d_in, const int* in_sizes, int n_in,
                              void* d_out, int out_size)
{
    const float* amount = (const float*)d_in[0];
    const int*   mcc    = (const int*)d_in[1];
    const int*   trt    = (const int*)d_in[2];
    const int*   seq    = (const int*)d_in[3];
    float*       out    = (float*)d_out;

    const int B = in_sizes[3];
    const int T = in_sizes[0] / B;

    cudaFuncSetAttribute(agg_kernel, cudaFuncAttributeMaxDynamicSharedMemorySize,
                         SMEM_BYTES);

    const int grid = (B + WARPS - 1) / WARPS;     // 12 rows (warps) per CTA
    agg_kernel<<<grid, WARPS * 32, SMEM_BYTES>>>(amount, mcc, trt, seq, out, B, T);
}